// round 5
// baseline (speedup 1.0000x reference)
#include <cuda_runtime.h>
#include <cuda_bf16.h>
#include <cstdint>

// MarginRankingLoss: x [V=4096, C=128, T=128] f32, target [V, C] int (32/64 bit).
// loss = sum_{v,c,t != tgt} max(0, x[v,c,t] - x[v,c,tgt] + 0.5) / (V*C*(T-1))
//
// Tricks:
//  - target position contributes exactly max(0, 0.5) = 0.5 -> sum over ALL t
//    branch-free and subtract ROWS*0.5 at the end.
//  - pos is extracted from the already-loaded row registers via shfl (no gather).
//  - single kernel: last block (atomicInc, self-resetting) reduces partials.

static constexpr long long V = 4096;
static constexpr long long C = 128;
static constexpr int       T = 128;
static constexpr long long ROWS = V * C;            // 524288
static constexpr float     MARGIN = 0.5f;

static constexpr int NBLOCKS       = 2048;
static constexpr int NTHREADS      = 256;
static constexpr int WARPS_PER_BLK = NTHREADS / 32;  // 8
static constexpr int NWARPS        = NBLOCKS * WARPS_PER_BLK;          // 16384
static constexpr int ROWS_PER_WARP = (int)(ROWS / NWARPS);             // 32

__device__ double   g_partials[NBLOCKS];
__device__ unsigned g_done;   // zero-initialized; atomicInc wraps back to 0

__global__ void __launch_bounds__(NTHREADS) mrl_kernel(
    const float* __restrict__ x,
    const void*  __restrict__ tgt_raw,
    float*       __restrict__ out)
{
    const unsigned FULL = 0xffffffffu;
    const int lane = threadIdx.x & 31;
    const int wid  = threadIdx.x >> 5;

    const float4* __restrict__ x4    = reinterpret_cast<const float4*>(x);
    const int*    __restrict__ tgt32 = reinterpret_cast<const int*>(tgt_raw);
    const long long* __restrict__ tgt64 = reinterpret_cast<const long long*>(tgt_raw);

    // ---- dtype detection (warp 0): int64 targets in [0,128) have zero
    // odd 32-bit words; int32 targets make P(all 32 sampled == 0) ~ 128^-32.
    __shared__ int sh_is64;
    if (threadIdx.x < 32) {
        int v = tgt32[2 * lane + 1];
        unsigned nz = __ballot_sync(FULL, v != 0);
        if (lane == 0) sh_is64 = (nz == 0u);
    }
    __syncthreads();
    const int is64 = sh_is64;

    // ---- main streaming loop: each warp owns 32 contiguous rows
    const int gwarp = blockIdx.x * WARPS_PER_BLK + wid;
    const long long row0 = (long long)gwarp * ROWS_PER_WARP;

    // one coalesced load of this warp's 32 targets (lane i -> row0+i)
    int t_lane = is64 ? (int)tgt64[row0 + lane] : tgt32[row0 + lane];
    t_lane &= (T - 1);

    float s = 0.0f;
    #pragma unroll 4
    for (int i = 0; i < ROWS_PER_WARP; i++) {
        const int t = __shfl_sync(FULL, t_lane, i);       // uniform target
        const float4 v = x4[(row0 + i) * (T / 4) + lane]; // coalesced LDG.128
        // extract x[row, t] from registers: lane t>>2 holds it, component t&3
        const int c = t & 3;
        float p = (c < 2) ? ((c == 0) ? v.x : v.y)
                          : ((c == 2) ? v.z : v.w);
        const float pos = __shfl_sync(FULL, p, t >> 2);
        const float b = pos - MARGIN;                     // hinge = max(0, v-b)
        s += fmaxf(v.x - b, 0.0f);
        s += fmaxf(v.y - b, 0.0f);
        s += fmaxf(v.z - b, 0.0f);
        s += fmaxf(v.w - b, 0.0f);
    }

    // ---- block reduction
    #pragma unroll
    for (int o = 16; o > 0; o >>= 1)
        s += __shfl_xor_sync(FULL, s, o);

    __shared__ double warp_sums[WARPS_PER_BLK];
    if (lane == 0) warp_sums[wid] = (double)s;
    __syncthreads();

    __shared__ bool sh_last;
    if (threadIdx.x == 0) {
        double bs = 0.0;
        #pragma unroll
        for (int i = 0; i < WARPS_PER_BLK; i++) bs += warp_sums[i];
        g_partials[blockIdx.x] = bs;
        __threadfence();
        // self-resetting: old == NBLOCKS-1 -> stored value wraps to 0
        unsigned old = atomicInc(&g_done, NBLOCKS - 1);
        sh_last = (old == NBLOCKS - 1);
    }
    __syncthreads();

    // ---- last block: deterministic final reduction
    if (sh_last) {
        double d = 0.0;
        #pragma unroll
        for (int i = threadIdx.x; i < NBLOCKS; i += NTHREADS)
            d += g_partials[i];
        // reduce 256 doubles
        __shared__ double dsh[WARPS_PER_BLK];
        #pragma unroll
        for (int o = 16; o > 0; o >>= 1)
            d += __shfl_xor_sync(FULL, d, o);
        if (lane == 0) dsh[wid] = d;
        __syncthreads();
        if (threadIdx.x == 0) {
            double tot = 0.0;
            #pragma unroll
            for (int i = 0; i < WARPS_PER_BLK; i++) tot += dsh[i];
            tot -= (double)ROWS * (double)MARGIN;  // remove target positions
            out[0] = (float)(tot / ((double)ROWS * (double)(T - 1)));
        }
    }
}

extern "C" void kernel_launch(void* const* d_in, const int* in_sizes, int n_in,
                              void* d_out, int out_size)
{
    const float* x   = (const float*)d_in[0];
    const void*  tgt = d_in[1];
    float*       out = (float*)d_out;

    mrl_kernel<<<NBLOCKS, NTHREADS>>>(x, tgt, out);
}